// round 13
// baseline (speedup 1.0000x reference)
#include <cuda_runtime.h>
#include <cuda_bf16.h>
#include <stdint.h>
#include <math.h>

#define Bsz  64
#define Tlen 256
#define Hdim 1024
#define Lnum 4
#define Odim 512
#define NBLK 128
#define NTHR 1024
#define NCHUNK 16
#define NSTEP (Tlen + Lnum - 1)    // 259 wavefront steps
#define ASTR 272                   // smem row pitch bytes
#define AHALF 17408u               // 64 rows * 272
#define ASLOT 34816u               // A hi+lo
#define WHALF 34816u               // 128 rows * 272
#define WSLOT 69632u               // W hi+lo

// ---- persistent device state ----
__device__ __nv_bfloat16 g_Whi[(size_t)Lnum * 32 * 16 * 128 * 128];  // 64 MB
__device__ __nv_bfloat16 g_Wlo[(size_t)Lnum * 32 * 16 * 128 * 128];  // 64 MB
__device__ __nv_bfloat16 g_xb_hi[(size_t)Tlen * 8 * 64 * 128];       // 32 MB
__device__ __nv_bfloat16 g_xb_lo[(size_t)Tlen * 8 * 64 * 128];       // 32 MB
__device__ __nv_bfloat16 g_hb_hi[Lnum * 2 * 8 * 64 * 128];           // 1 MB
__device__ __nv_bfloat16 g_hb_lo[Lnum * 2 * 8 * 64 * 128];           // 1 MB
__device__ float g_hfin[Bsz * Hdim];

__device__ volatile unsigned g_gen = 0;
__device__ unsigned g_count = 0;

__device__ __forceinline__ void grid_sync() {
    __syncthreads();
    if (threadIdx.x == 0) {
        __threadfence();
        unsigned my = g_gen;
        if (atomicAdd(&g_count, 1u) == NBLK - 1) {
            g_count = 0; __threadfence(); g_gen = my + 1;
        } else {
            while (g_gen == my) { __nanosleep(20); }
        }
        __threadfence();
    }
    __syncthreads();
}

__device__ __forceinline__ uint32_t smem_u32(const void* p) {
    uint32_t a;
    asm("{ .reg .u64 t; cvta.to.shared.u64 t, %1; cvt.u32.u64 %0, t; }"
        : "=r"(a) : "l"(p));
    return a;
}
__device__ __forceinline__ float ex2f(float x) {
    float r; asm("ex2.approx.f32 %0, %1;" : "=f"(r) : "f"(x)); return r;
}
__device__ __forceinline__ float rcpf(float x) {
    float r; asm("rcp.approx.f32 %0, %1;" : "=f"(r) : "f"(x)); return r;
}
__device__ __forceinline__ float sigf(float x) {
    return rcpf(1.0f + ex2f(-1.4426950408889634f * x));
}
__device__ __forceinline__ float tanhfast(float x) {
    float e = ex2f(2.8853900817779268f * x);
    return 1.0f - 2.0f * rcpf(e + 1.0f);
}

#define LDSM4(r, a)                                                           \
    asm volatile("ldmatrix.sync.aligned.m8n8.x4.shared.b16 {%0,%1,%2,%3}, [%4];" \
        : "=r"((r)[0]), "=r"((r)[1]), "=r"((r)[2]), "=r"((r)[3]) : "r"(a))

#define MMA(d, a, b0, b1)                                                     \
    asm volatile("mma.sync.aligned.m16n8k16.row.col.f32.bf16.bf16.f32 "       \
        "{%0,%1,%2,%3},{%4,%5,%6,%7},{%8,%9},{%0,%1,%2,%3};"                  \
        : "+f"((d)[0]), "+f"((d)[1]), "+f"((d)[2]), "+f"((d)[3])              \
        : "r"((a)[0]), "r"((a)[1]), "r"((a)[2]), "r"((a)[3]),                 \
          "r"(b0), "r"(b1))

#define CPA16(dst, src) \
    asm volatile("cp.async.ca.shared.global [%0], [%1], 16;" :: "r"(dst), "l"(src))
#define CPA_COMMIT() asm volatile("cp.async.commit_group;" ::: "memory")
#define CPA_WAIT(n)  asm volatile("cp.async.wait_group %0;" :: "n"(n) : "memory")

// smem: bias[128] | c[64][32] | 2 A slots | 2 W slots
#define OFF_BIAS 0
#define OFF_C    512
#define OFF_A    8704
#define OFF_W    78336                    // 8704 + 2*34816
#define SMEM_DYN 217600                   // 78336 + 2*69632

__global__ void zero_hb() {
    int i = blockIdx.x * 1024 + threadIdx.x;      // grid 512
    g_hb_hi[i] = __float2bfloat16(0.f);
    g_hb_lo[i] = __float2bfloat16(0.f);
}

__global__ void prep_x(const float* __restrict__ x) {
    size_t idx = (size_t)blockIdx.x * 1024 + threadIdx.x;   // 2^24
    int c  = (int)(idx & 127);
    int b  = (int)((idx >> 7) & 63);
    int ck = (int)((idx >> 13) & 7);
    int t  = (int)(idx >> 16);
    float v = x[((size_t)b * Tlen + t) * 1024 + ck * 128 + c];
    __nv_bfloat16 h = __float2bfloat16(v);
    size_t dst = (((size_t)(t * 8 + ck)) * 64 + b) * 128 + c;
    g_xb_hi[dst] = h;
    g_xb_lo[dst] = __float2bfloat16(v - __bfloat162float(h));
}

__global__ void prep_weights(const float* __restrict__ Wih,
                             const float* __restrict__ Whh) {
    size_t idx = (size_t)blockIdx.x * 1024 + threadIdx.x;   // 2^25
    int c  = (int)(idx & 127);
    int n  = (int)((idx >> 7) & 127);
    int ck = (int)((idx >> 14) & 15);
    int nb = (int)((idx >> 18) & 31);
    int l  = (int)(idx >> 23);
    int gate = n >> 5, hid = nb * 32 + (n & 31);
    int kk = ck * 128 + c;
    size_t grow = (size_t)l * 4096 * 1024 + (size_t)(gate * 1024 + hid) * 1024;
    float v = (kk < 1024) ? Wih[grow + kk] : Whh[grow + kk - 1024];
    __nv_bfloat16 h = __float2bfloat16(v);
    size_t e = ((((size_t)l * 32 + nb) * 16) + ck) * 16384 + (size_t)n * 128 + c;
    g_Whi[e] = h;
    g_Wlo[e] = __float2bfloat16(v - __bfloat162float(h));
}

__global__ __launch_bounds__(NTHR, 1) void lstm_persistent(
    const float* __restrict__ bih, const float* __restrict__ bhh)
{
    extern __shared__ char sm[];
    const uint32_t sbase = smem_u32(sm);

    const int tid  = threadIdx.x;
    const int wid  = tid >> 5;
    const int lane = tid & 31;
    const int bx   = blockIdx.x;
    const int L    = bx >> 5;            // this block's layer
    const int nb   = bx & 31;
    const int n0   = nb * 32;            // first hidden unit
    // warp tiling: 4m(16) x 4n(32) x 2kg(4 k-steps each), 32 warps
    const int mt = wid & 3;
    const int nt = (wid >> 2) & 3;
    const int kg = wid >> 4;

    if (tid < 128) {
        int gate = tid >> 5, hid = n0 + (tid & 31);
        int row = L * 4096 + gate * 1024 + hid;
        ((float*)(sm + OFF_BIAS))[tid] = bih[row] + bhh[row];
    }
    float* csm = (float*)(sm + OFF_C);   // [64][32]
    #pragma unroll
    for (int i = 0; i < 2; ++i)
        csm[i * 1024 + tid] = 0.f;
    __syncthreads();

    // ldmatrix per-lane offsets
    const uint32_t a_off  = (uint32_t)(mt * 16 + (lane & 15)) * ASTR
                          + ((uint32_t)(lane >> 4) << 4);
    const uint32_t b_off0 = (uint32_t)(nt * 32 + (lane & 7) + ((lane >> 4) << 3)) * ASTR
                          + (((uint32_t)(lane >> 3) & 1u) << 4);
    const uint32_t b_off1 = b_off0 + 16u * ASTR;
    // cp.async dest offsets (1024 threads): W-half 32KB = 2 ops, A-half 16KB = 1 op
    uint32_t wdo[2];
    #pragma unroll
    for (int i = 0; i < 2; ++i) {
        int u = i * 1024 + tid;
        wdo[i] = (uint32_t)(u >> 4) * ASTR + (uint32_t)(u & 15) * 16;
    }
    const uint32_t ado = wdo[0];
    const uint32_t kb0 = (uint32_t)kg * 128;   // 4 k-steps * 32B

    const char* wBaseHi = (const char*)(g_Whi + (((size_t)L * 32 + nb) * 16) * 16384);
    const char* wBaseLo = (const char*)(g_Wlo + (((size_t)L * 32 + nb) * 16) * 16384);

    // prefetch W for chunks 0,1 into W slots (group P) — W addr is static
    #define PREF_W() do {                                                     \
        _Pragma("unroll")                                                     \
        for (int sq = 0; sq < 2; ++sq) {                                      \
            uint32_t wB = sbase + OFF_W + (uint32_t)sq * WSLOT;               \
            const char* wh_ = wBaseHi + (size_t)sq * 32768;                   \
            const char* wl_ = wBaseLo + (size_t)sq * 32768;                   \
            _Pragma("unroll")                                                 \
            for (int i_ = 0; i_ < 2; ++i_) {                                  \
                CPA16(wB + wdo[i_], wh_ + (size_t)(i_ * 1024 + tid) * 16);    \
                CPA16(wB + WHALF + wdo[i_],                                   \
                      wl_ + (size_t)(i_ * 1024 + tid) * 16);                  \
            }                                                                 \
        }                                                                     \
    } while (0)

    PREF_W(); CPA_COMMIT();   // group P (persists across inactive steps)

    for (int s = 0; s < NSTEP; ++s) {
        const int t = s - L;
        if (0 <= t && t < Tlen) {
            const int par = t & 1;
            const char *blHi, *blLo;
            if (L == 0) {
                blHi = (const char*)(g_xb_hi + (size_t)t * 8 * 8192);
                blLo = (const char*)(g_xb_lo + (size_t)t * 8 * 8192);
            } else {
                size_t o = (size_t)((L - 1) * 2 + par) * 8 * 8192;
                blHi = (const char*)(g_hb_hi + o);
                blLo = (const char*)(g_hb_lo + o);
            }
            size_t oh = (size_t)(L * 2 + (par ^ 1)) * 8 * 8192;
            const char* bhHi = (const char*)(g_hb_hi + oh);
            const char* bhLo = (const char*)(g_hb_lo + oh);

            float acc[4][4] = {};   // 4 n-subtiles x 4 regs (merged 3 passes)

            #define SRC_A_HI(ck) (((ck) < 8) ? blHi + (size_t)(ck) * 16384    \
                                             : bhHi + (size_t)((ck) - 8) * 16384)
            #define SRC_A_LO(ck) (((ck) < 8) ? blLo + (size_t)(ck) * 16384    \
                                             : bhLo + (size_t)((ck) - 8) * 16384)

            #define ISSUE_A(ck, slot) do {                                    \
                uint32_t aB = sbase + OFF_A + (uint32_t)(slot) * ASLOT;       \
                CPA16(aB + ado, SRC_A_HI(ck) + (size_t)tid * 16);             \
                CPA16(aB + AHALF + ado, SRC_A_LO(ck) + (size_t)tid * 16);     \
            } while (0)

            #define ISSUE_FULL(ck, slot) do {                                 \
                const char* wh_ = wBaseHi + (size_t)(ck) * 32768;             \
                const char* wl_ = wBaseLo + (size_t)(ck) * 32768;             \
                uint32_t wB = sbase + OFF_W + (uint32_t)(slot) * WSLOT;       \
                _Pragma("unroll")                                             \
                for (int i_ = 0; i_ < 2; ++i_) {                              \
                    CPA16(wB + wdo[i_], wh_ + (size_t)(i_ * 1024 + tid) * 16); \
                    CPA16(wB + WHALF + wdo[i_],                               \
                          wl_ + (size_t)(i_ * 1024 + tid) * 16);              \
                }                                                             \
                ISSUE_A(ck, slot);                                            \
            } while (0)

            ISSUE_A(0, 0); CPA_COMMIT();   // QA0 (W for ck0 came from P)
            ISSUE_A(1, 1); CPA_COMMIT();   // QA1

            for (int ck = 0; ck < NCHUNK; ++ck) {
                const int slot = ck & 1;
                __syncthreads();           // compute(ck-1) done -> slot^1 free
                if (ck >= 1 && ck + 1 < NCHUNK) {
                    ISSUE_FULL(ck + 1, (ck + 1) & 1);
                    CPA_COMMIT();
                }
                if (ck < NCHUNK - 1) CPA_WAIT(1);
                else                 CPA_WAIT(0);
                __syncthreads();           // ck visible to all warps

                const uint32_t aH = sbase + OFF_A + (uint32_t)slot * ASLOT;
                const uint32_t aL = aH + AHALF;
                const uint32_t wH = sbase + OFF_W + (uint32_t)slot * WSLOT;
                const uint32_t wL = wH + WHALF;
                #pragma unroll
                for (int kk = 0; kk < 4; ++kk) {
                    const uint32_t kb = kb0 + (uint32_t)kk * 32;
                    uint32_t ah[4], al[4], bh0[4], bh1[4], bl0[4], bl1[4];
                    LDSM4(ah,  aH + a_off + kb);
                    LDSM4(al,  aL + a_off + kb);
                    LDSM4(bh0, wH + b_off0 + kb);
                    LDSM4(bh1, wH + b_off1 + kb);
                    LDSM4(bl0, wL + b_off0 + kb);
                    LDSM4(bl1, wL + b_off1 + kb);
                    MMA(acc[0], ah, bh0[0], bh0[1]);
                    MMA(acc[1], ah, bh0[2], bh0[3]);
                    MMA(acc[2], ah, bh1[0], bh1[1]);
                    MMA(acc[3], ah, bh1[2], bh1[3]);
                    MMA(acc[0], al, bh0[0], bh0[1]);
                    MMA(acc[1], al, bh0[2], bh0[3]);
                    MMA(acc[2], al, bh1[0], bh1[1]);
                    MMA(acc[3], al, bh1[2], bh1[3]);
                    MMA(acc[0], ah, bl0[0], bl0[1]);
                    MMA(acc[1], ah, bl0[2], bl0[3]);
                    MMA(acc[2], ah, bl1[0], bl1[1]);
                    MMA(acc[3], ah, bl1[2], bl1[3]);
                }
            }
            #undef ISSUE_FULL
            #undef ISSUE_A
            #undef SRC_A_HI
            #undef SRC_A_LO

            __syncthreads();   // all warps done reading A+W slots

            // prefetch next step's W (static addr) — overlaps epilogue+sync
            PREF_W(); CPA_COMMIT();

            // partial gates per k-group: Gs[2][64][132] (fits A region)
            float* Gs = (float*)(sm + OFF_A);
            #pragma unroll
            for (int ni = 0; ni < 4; ++ni) {
                int R = mt * 16 + (lane >> 2);
                int C = nt * 32 + ni * 8 + (lane & 3) * 2;
                int base = (kg * 64 + R) * 132 + C;
                Gs[base]               = acc[ni][0];
                Gs[base + 1]           = acc[ni][1];
                Gs[base + 8 * 132]     = acc[ni][2];
                Gs[base + 8 * 132 + 1] = acc[ni][3];
            }
            __syncthreads();

            {
                const float* bias = (const float*)(sm + OFF_BIAS);
                const int ckd = nb >> 2;
                #pragma unroll
                for (int q = 0; q < 2; ++q) {
                    int e = q * 1024 + tid;          // 0..2047
                    int b = e >> 5, hl = e & 31;
                    float gi = Gs[b * 132 + hl]      + Gs[(64 + b) * 132 + hl]
                             + bias[hl];
                    float gf = Gs[b * 132 + 32 + hl] + Gs[(64 + b) * 132 + 32 + hl]
                             + bias[32 + hl];
                    float gg = Gs[b * 132 + 64 + hl] + Gs[(64 + b) * 132 + 64 + hl]
                             + bias[64 + hl];
                    float go = Gs[b * 132 + 96 + hl] + Gs[(64 + b) * 132 + 96 + hl]
                             + bias[96 + hl];
                    float ig = sigf(gi), fg = sigf(gf), og = sigf(go);
                    float gt = tanhfast(gg);
                    float* cp_ = csm + b * 32 + hl;
                    float cn = fg * (*cp_) + ig * gt;
                    *cp_ = cn;
                    float hn = og * tanhfast(cn);
                    __nv_bfloat16 hh = __float2bfloat16(hn);
                    __nv_bfloat16 hlw = __float2bfloat16(hn - __bfloat162float(hh));
                    int coltile = (nb & 3) * 32 + hl;
                    size_t off = ((((size_t)(L * 2 + par) * 8 + ckd) * 64 + b) * 128)
                               + coltile;
                    g_hb_hi[off] = hh;
                    g_hb_lo[off] = hlw;
                    if (t == Tlen - 1 && L == Lnum - 1)
                        g_hfin[(size_t)b * Hdim + n0 + hl] = hn;
                }
            }
        }
        grid_sync();
    }
}

__global__ void fc_kernel(const float* __restrict__ Wfc,
                          const float* __restrict__ bfc,
                          float* __restrict__ out)
{
    const float* h = g_hfin;
    int warp = (blockIdx.x * blockDim.x + threadIdx.x) >> 5;
    int lane = threadIdx.x & 31;
    int b = warp >> 9;
    int o = warp & (Odim - 1);
    const float4* hv = (const float4*)(h   + (size_t)b * Hdim);
    const float4* wv = (const float4*)(Wfc + (size_t)o * Hdim);
    float s = 0.f;
    #pragma unroll
    for (int it = 0; it < 8; ++it) {
        float4 a = hv[it * 32 + lane];
        float4 w = wv[it * 32 + lane];
        s += a.x * w.x + a.y * w.y + a.z * w.z + a.w * w.w;
    }
    #pragma unroll
    for (int off = 16; off; off >>= 1)
        s += __shfl_xor_sync(0xffffffffu, s, off);
    if (lane == 0)
        out[(size_t)b * Odim + o] = s + bfc[o];
}

extern "C" void kernel_launch(void* const* d_in, const int* in_sizes, int n_in,
                              void* d_out, int out_size)
{
    const float* x   = (const float*)d_in[0];
    const float* Wih = (const float*)d_in[1];
    const float* Whh = (const float*)d_in[2];
    const float* bih = (const float*)d_in[3];
    const float* bhh = (const float*)d_in[4];
    const float* Wfc = (const float*)d_in[5];
    const float* bfc = (const float*)d_in[6];
    float* out = (float*)d_out;

    cudaFuncSetAttribute(lstm_persistent,
                         cudaFuncAttributeMaxDynamicSharedMemorySize, SMEM_DYN);

    zero_hb<<<512, 1024>>>();
    prep_x<<<16384, 1024>>>(x);
    prep_weights<<<32768, 1024>>>(Wih, Whh);
    lstm_persistent<<<NBLK, NTHR, SMEM_DYN>>>(bih, bhh);
    fc_kernel<<<(Bsz * Odim) / 8, 256>>>(Wfc, bfc, out);
}

// round 14
// speedup vs baseline: 1.1892x; 1.1892x over previous
#include <cuda_runtime.h>
#include <cuda_bf16.h>
#include <stdint.h>
#include <math.h>

#define Bsz  64
#define Tlen 256
#define Hdim 1024
#define Lnum 4
#define Odim 512
#define NBLK 128
#define NTHR 512
#define NCHUNK 16
#define NSTEP (Tlen + Lnum - 1)    // 259 wavefront steps
#define ASTR 272                   // A smem row pitch bytes
#define AHALF 17408u               // 64 rows * 272
#define ASLOT 34816u               // A hi+lo per chunk

// ---- persistent device state ----
// W in MMA B-fragment order: per (l,nb): [ck 16][kkg 8][nt 4][lane 32][j 4][reg 2]
// = 512 KB per (l,nb) per array.
__device__ __align__(16) unsigned g_Whi[(size_t)Lnum * 32 * 131072];   // 64 MB
__device__ __align__(16) unsigned g_Wlo[(size_t)Lnum * 32 * 131072];   // 64 MB
__device__ __align__(16) __nv_bfloat16 g_xb_hi[(size_t)Tlen * 8 * 64 * 128]; // 32 MB
__device__ __align__(16) __nv_bfloat16 g_xb_lo[(size_t)Tlen * 8 * 64 * 128]; // 32 MB
__device__ __align__(16) __nv_bfloat16 g_hb_hi[Lnum * 2 * 8 * 64 * 128];     // 1 MB
__device__ __align__(16) __nv_bfloat16 g_hb_lo[Lnum * 2 * 8 * 64 * 128];     // 1 MB
__device__ float g_hfin[Bsz * Hdim];

__device__ volatile unsigned g_gen = 0;
__device__ unsigned g_count = 0;

__device__ __forceinline__ void grid_sync() {
    __syncthreads();
    if (threadIdx.x == 0) {
        __threadfence();
        unsigned my = g_gen;
        if (atomicAdd(&g_count, 1u) == NBLK - 1) {
            g_count = 0; __threadfence(); g_gen = my + 1;
        } else {
            while (g_gen == my) { __nanosleep(20); }
        }
        __threadfence();
    }
    __syncthreads();
}

__device__ __forceinline__ uint32_t smem_u32(const void* p) {
    uint32_t a;
    asm("{ .reg .u64 t; cvta.to.shared.u64 t, %1; cvt.u32.u64 %0, t; }"
        : "=r"(a) : "l"(p));
    return a;
}
__device__ __forceinline__ float ex2f(float x) {
    float r; asm("ex2.approx.f32 %0, %1;" : "=f"(r) : "f"(x)); return r;
}
__device__ __forceinline__ float rcpf(float x) {
    float r; asm("rcp.approx.f32 %0, %1;" : "=f"(r) : "f"(x)); return r;
}
__device__ __forceinline__ float sigf(float x) {
    return rcpf(1.0f + ex2f(-1.4426950408889634f * x));
}
__device__ __forceinline__ float tanhfast(float x) {
    float e = ex2f(2.8853900817779268f * x);
    return 1.0f - 2.0f * rcpf(e + 1.0f);
}

#define LDSM4(r, a)                                                           \
    asm volatile("ldmatrix.sync.aligned.m8n8.x4.shared.b16 {%0,%1,%2,%3}, [%4];" \
        : "=r"((r)[0]), "=r"((r)[1]), "=r"((r)[2]), "=r"((r)[3]) : "r"(a))

#define MMA(d, a, b0, b1)                                                     \
    asm volatile("mma.sync.aligned.m16n8k16.row.col.f32.bf16.bf16.f32 "       \
        "{%0,%1,%2,%3},{%4,%5,%6,%7},{%8,%9},{%0,%1,%2,%3};"                  \
        : "+f"((d)[0]), "+f"((d)[1]), "+f"((d)[2]), "+f"((d)[3])              \
        : "r"((a)[0]), "r"((a)[1]), "r"((a)[2]), "r"((a)[3]),                 \
          "r"(b0), "r"(b1))

#define LDG128CG(q, p)                                                        \
    asm volatile("ld.global.cg.v4.u32 {%0,%1,%2,%3}, [%4];"                   \
        : "=r"((q).x), "=r"((q).y), "=r"((q).z), "=r"((q).w)                  \
        : "l"(p))

#define CPA16(dst, src) \
    asm volatile("cp.async.ca.shared.global [%0], [%1], 16;" :: "r"(dst), "l"(src))
#define CPA_COMMIT() asm volatile("cp.async.commit_group;" ::: "memory")
#define CPA_WAIT(n)  asm volatile("cp.async.wait_group %0;" :: "n"(n) : "memory")

// smem: bias[128] | c[64][32] | 4 A slots
#define OFF_BIAS 0
#define OFF_C    512
#define OFF_A    8704
#define SMEM_DYN (8704 + 4 * 34816)      // 147968

__global__ void zero_hb() {
    int i = blockIdx.x * 1024 + threadIdx.x;      // grid 512
    g_hb_hi[i] = __float2bfloat16(0.f);
    g_hb_lo[i] = __float2bfloat16(0.f);
}

__global__ void prep_x(const float* __restrict__ x) {
    size_t idx = (size_t)blockIdx.x * 1024 + threadIdx.x;   // 2^24
    int c  = (int)(idx & 127);
    int b  = (int)((idx >> 7) & 63);
    int ck = (int)((idx >> 13) & 7);
    int t  = (int)(idx >> 16);
    float v = x[((size_t)b * Tlen + t) * 1024 + ck * 128 + c];
    __nv_bfloat16 h = __float2bfloat16(v);
    size_t dst = (((size_t)(t * 8 + ck)) * 64 + b) * 128 + c;
    g_xb_hi[dst] = h;
    g_xb_lo[dst] = __float2bfloat16(v - __bfloat162float(h));
}

// Write W in MMA B-fragment order (hi/lo split). One thread per uint32 (2 elems).
__global__ void prep_weights(const float* __restrict__ Wih,
                             const float* __restrict__ Whh) {
    unsigned idx = blockIdx.x * 1024 + threadIdx.x;   // 2^24
    int reg  = idx & 1;
    int j    = (idx >> 1) & 3;
    int lane = (idx >> 3) & 31;
    int nt   = (idx >> 8) & 3;
    int kkg  = (idx >> 10) & 7;
    int ck   = (idx >> 13) & 15;
    int nb   = (idx >> 17) & 31;
    int l    = (idx >> 22) & 3;

    int n_local = nt * 32 + j * 8 + (lane >> 2);          // 0..127 gate col
    int k_local = kkg * 16 + (lane & 3) * 2 + reg * 8;    // even k
    int gate = n_local >> 5, hid = nb * 32 + (n_local & 31);
    size_t grow = (size_t)l * 4096 * 1024 + (size_t)(gate * 1024 + hid) * 1024;
    int k0 = ck * 128 + k_local;

    float v0 = (k0 < 1024)     ? Wih[grow + k0]     : Whh[grow + k0 - 1024];
    float v1 = (k0 + 1 < 1024) ? Wih[grow + k0 + 1] : Whh[grow + k0 + 1 - 1024];
    __nv_bfloat16 h0 = __float2bfloat16(v0), h1 = __float2bfloat16(v1);
    __nv_bfloat16 l0 = __float2bfloat16(v0 - __bfloat162float(h0));
    __nv_bfloat16 l1 = __float2bfloat16(v1 - __bfloat162float(h1));
    union { __nv_bfloat162 b; unsigned u; } qh, ql;
    qh.b = __halves2bfloat162(h0, h1);
    ql.b = __halves2bfloat162(l0, l1);

    size_t off = ((size_t)l * 32 + nb) * 131072
               + (size_t)((((ck * 8 + kkg) * 4 + nt) * 32 + lane) * 8 + j * 2 + reg);
    g_Whi[off] = qh.u;
    g_Wlo[off] = ql.u;
}

__global__ __launch_bounds__(NTHR, 1) void lstm_persistent(
    const float* __restrict__ bih, const float* __restrict__ bhh)
{
    extern __shared__ char sm[];
    const uint32_t sbase = smem_u32(sm);

    const int tid  = threadIdx.x;
    const int wid  = tid >> 5;
    const int lane = tid & 31;
    const int bx   = blockIdx.x;
    const int L    = bx >> 5;
    const int nb   = bx & 31;
    const int n0   = nb * 32;
    // 16 warps = 2m(32) x 4n(32) x 2kg(4 k-steps)
    const int mt = wid & 1;
    const int nt = (wid >> 1) & 3;
    const int kg = wid >> 3;

    if (tid < 128) {
        int gate = tid >> 5, hid = n0 + (tid & 31);
        int row = L * 4096 + gate * 1024 + hid;
        ((float*)(sm + OFF_BIAS))[tid] = bih[row] + bhh[row];
    }
    float* csm = (float*)(sm + OFF_C);   // [64][32]
    #pragma unroll
    for (int i = 0; i < 4; ++i)
        csm[i * NTHR + tid] = 0.f;
    __syncthreads();

    // A ldmatrix per-lane offsets (m32 per warp: two m16 frags)
    const uint32_t a_off0 = (uint32_t)(mt * 32 + (lane & 15)) * ASTR
                          + ((uint32_t)(lane >> 4) << 4);
    const uint32_t a_off1 = a_off0 + 16u * ASTR;
    // A cp.async dest offsets (512 thr: 2 x 16B per half)
    uint32_t ado[2];
    #pragma unroll
    for (int i = 0; i < 2; ++i) {
        int u = i * 512 + tid;
        ado[i] = (uint32_t)(u >> 4) * ASTR + (uint32_t)(u & 15) * 16;
    }
    const uint32_t kb0 = (uint32_t)kg * 128;   // byte offset of first k-step

    const char* whiT = (const char*)(g_Whi + ((size_t)L * 32 + nb) * 131072);
    const char* wloT = (const char*)(g_Wlo + ((size_t)L * 32 + nb) * 131072);
    // B fragment byte offset for (ck, kk in 0..3)
    #define BOFF(ck, kk) ((size_t)((((ck) * 8 + kg * 4 + (kk)) * 4 + nt) << 10) \
                          + (size_t)lane * 32)

    for (int s = 0; s < NSTEP; ++s) {
        const int t = s - L;
        if (0 <= t && t < Tlen) {
            const int par = t & 1;
            const char *blHi, *blLo;
            if (L == 0) {
                blHi = (const char*)(g_xb_hi + (size_t)t * 8 * 8192);
                blLo = (const char*)(g_xb_lo + (size_t)t * 8 * 8192);
            } else {
                size_t o = (size_t)((L - 1) * 2 + par) * 8 * 8192;
                blHi = (const char*)(g_hb_hi + o);
                blLo = (const char*)(g_hb_lo + o);
            }
            size_t oh = (size_t)(L * 2 + (par ^ 1)) * 8 * 8192;
            const char* bhHi = (const char*)(g_hb_hi + oh);
            const char* bhLo = (const char*)(g_hb_lo + oh);

            float acc0[4][4] = {}, acc1[4][4] = {};   // [m-frag][n-frag][4]

            #define SRC_A_HI(ck) (((ck) < 8) ? blHi + (size_t)(ck) * 16384    \
                                             : bhHi + (size_t)((ck) - 8) * 16384)
            #define SRC_A_LO(ck) (((ck) < 8) ? blLo + (size_t)(ck) * 16384    \
                                             : bhLo + (size_t)((ck) - 8) * 16384)
            #define ISSUE_A(ck, slot) do {                                    \
                uint32_t aB = sbase + OFF_A + (uint32_t)(slot) * ASLOT;       \
                _Pragma("unroll")                                             \
                for (int i_ = 0; i_ < 2; ++i_) {                              \
                    CPA16(aB + ado[i_],                                       \
                          SRC_A_HI(ck) + (size_t)(i_ * 512 + tid) * 16);      \
                    CPA16(aB + AHALF + ado[i_],                               \
                          SRC_A_LO(ck) + (size_t)(i_ * 512 + tid) * 16);      \
                }                                                             \
            } while (0)

            // prologue: 3 A chunks in flight
            ISSUE_A(0, 0); CPA_COMMIT();
            ISSUE_A(1, 1); CPA_COMMIT();
            ISSUE_A(2, 2); CPA_COMMIT();

            // B pipeline: load (0,0) fragments
            uint4 qh0, qh1, ql0, ql1;
            {
                size_t o = BOFF(0, 0);
                LDG128CG(qh0, (const uint4*)(whiT + o));
                LDG128CG(qh1, (const uint4*)(whiT + o + 16));
                LDG128CG(ql0, (const uint4*)(wloT + o));
                LDG128CG(ql1, (const uint4*)(wloT + o + 16));
            }

            for (int ck = 0; ck < NCHUNK; ++ck) {
                const int slot = ck & 3;
                if (ck <= 13)      CPA_WAIT(2);   // group(ck) landed
                else if (ck == 14) CPA_WAIT(1);
                else               CPA_WAIT(0);
                __syncthreads();                  // visibility + slot reuse
                if (ck + 3 < NCHUNK) {
                    ISSUE_A(ck + 3, (ck + 3) & 3);
                    CPA_COMMIT();
                }

                const uint32_t aH = sbase + OFF_A + (uint32_t)slot * ASLOT;
                const uint32_t aL = aH + AHALF;
                #pragma unroll
                for (int kk = 0; kk < 4; ++kk) {
                    uint4 nh0, nh1, nl0, nl1;
                    const bool last = (ck == NCHUNK - 1) && (kk == 3);
                    if (!last) {
                        int nck = (kk == 3) ? ck + 1 : ck;
                        int nkk = (kk == 3) ? 0 : kk + 1;
                        size_t o = BOFF(nck, nkk);
                        LDG128CG(nh0, (const uint4*)(whiT + o));
                        LDG128CG(nh1, (const uint4*)(whiT + o + 16));
                        LDG128CG(nl0, (const uint4*)(wloT + o));
                        LDG128CG(nl1, (const uint4*)(wloT + o + 16));
                    }
                    const uint32_t kb = kb0 + (uint32_t)kk * 32;
                    uint32_t ah0[4], ah1[4], al0[4], al1[4];
                    LDSM4(ah0, aH + a_off0 + kb);
                    LDSM4(ah1, aH + a_off1 + kb);
                    LDSM4(al0, aL + a_off0 + kb);
                    LDSM4(al1, aL + a_off1 + kb);
                    // hi*hi
                    MMA(acc0[0], ah0, qh0.x, qh0.y);
                    MMA(acc0[1], ah0, qh0.z, qh0.w);
                    MMA(acc0[2], ah0, qh1.x, qh1.y);
                    MMA(acc0[3], ah0, qh1.z, qh1.w);
                    MMA(acc1[0], ah1, qh0.x, qh0.y);
                    MMA(acc1[1], ah1, qh0.z, qh0.w);
                    MMA(acc1[2], ah1, qh1.x, qh1.y);
                    MMA(acc1[3], ah1, qh1.z, qh1.w);
                    // lo*hi
                    MMA(acc0[0], al0, qh0.x, qh0.y);
                    MMA(acc0[1], al0, qh0.z, qh0.w);
                    MMA(acc0[2], al0, qh1.x, qh1.y);
                    MMA(acc0[3], al0, qh1.z, qh1.w);
                    MMA(acc1[0], al1, qh0.x, qh0.y);
                    MMA(acc1[1], al1, qh0.z, qh0.w);
                    MMA(acc1[2], al1, qh1.x, qh1.y);
                    MMA(acc1[3], al1, qh1.z, qh1.w);
                    // hi*lo
                    MMA(acc0[0], ah0, ql0.x, ql0.y);
                    MMA(acc0[1], ah0, ql0.z, ql0.w);
                    MMA(acc0[2], ah0, ql1.x, ql1.y);
                    MMA(acc0[3], ah0, ql1.z, ql1.w);
                    MMA(acc1[0], ah1, ql0.x, ql0.y);
                    MMA(acc1[1], ah1, ql0.z, ql0.w);
                    MMA(acc1[2], ah1, ql1.x, ql1.y);
                    MMA(acc1[3], ah1, ql1.z, ql1.w);
                    if (!last) { qh0 = nh0; qh1 = nh1; ql0 = nl0; ql1 = nl1; }
                }
            }
            #undef ISSUE_A
            #undef SRC_A_HI
            #undef SRC_A_LO

            // epilogue: Gs[2][64][132] = 67584 B, fits in A slots 0-1 region.
            // Safe without a barrier: lagging warps read slots 2/3 only.
            float* Gs = (float*)(sm + OFF_A);
            #pragma unroll
            for (int mi = 0; mi < 2; ++mi) {
                float (*am)[4] = mi ? acc1 : acc0;
                #pragma unroll
                for (int ni = 0; ni < 4; ++ni) {
                    int R = mt * 32 + mi * 16 + (lane >> 2);
                    int C = nt * 32 + ni * 8 + (lane & 3) * 2;
                    int base = (kg * 64 + R) * 132 + C;
                    Gs[base]               = am[ni][0];
                    Gs[base + 1]           = am[ni][1];
                    Gs[base + 8 * 132]     = am[ni][2];
                    Gs[base + 8 * 132 + 1] = am[ni][3];
                }
            }
            __syncthreads();

            {
                const float* bias = (const float*)(sm + OFF_BIAS);
                const int ckd = nb >> 2;
                #pragma unroll
                for (int q = 0; q < 4; ++q) {
                    int e = q * 512 + tid;          // 0..2047
                    int b = e >> 5, hl = e & 31;
                    float gi = Gs[b * 132 + hl]      + Gs[(64 + b) * 132 + hl]
                             + bias[hl];
                    float gf = Gs[b * 132 + 32 + hl] + Gs[(64 + b) * 132 + 32 + hl]
                             + bias[32 + hl];
                    float gg = Gs[b * 132 + 64 + hl] + Gs[(64 + b) * 132 + 64 + hl]
                             + bias[64 + hl];
                    float go = Gs[b * 132 + 96 + hl] + Gs[(64 + b) * 132 + 96 + hl]
                             + bias[96 + hl];
                    float ig = sigf(gi), fg = sigf(gf), og = sigf(go);
                    float gt = tanhfast(gg);
                    float* cp_ = csm + b * 32 + hl;
                    float cn = fg * (*cp_) + ig * gt;
                    *cp_ = cn;
                    float hn = og * tanhfast(cn);
                    __nv_bfloat16 hh = __float2bfloat16(hn);
                    __nv_bfloat16 hlw = __float2bfloat16(hn - __bfloat162float(hh));
                    int coltile = (nb & 3) * 32 + hl;
                    size_t off = ((((size_t)(L * 2 + par) * 8 + ckd) * 64 + b) * 128)
                               + coltile;
                    g_hb_hi[off] = hh;
                    g_hb_lo[off] = hlw;
                    if (t == Tlen - 1 && L == Lnum - 1)
                        g_hfin[(size_t)b * Hdim + n0 + hl] = hn;
                }
            }
        }
        grid_sync();
    }
    #undef BOFF
}

__global__ void fc_kernel(const float* __restrict__ Wfc,
                          const float* __restrict__ bfc,
                          float* __restrict__ out)
{
    const float* h = g_hfin;
    int warp = (blockIdx.x * blockDim.x + threadIdx.x) >> 5;
    int lane = threadIdx.x & 31;
    int b = warp >> 9;
    int o = warp & (Odim - 1);
    const float4* hv = (const float4*)(h   + (size_t)b * Hdim);
    const float4* wv = (const float4*)(Wfc + (size_t)o * Hdim);
    float s = 0.f;
    #pragma unroll
    for (int it = 0; it < 8; ++it) {
        float4 a = hv[it * 32 + lane];
        float4 w = wv[it * 32 + lane];
        s += a.x * w.x + a.y * w.y + a.z * w.z + a.w * w.w;
    }
    #pragma unroll
    for (int off = 16; off; off >>= 1)
        s += __shfl_xor_sync(0xffffffffu, s, off);
    if (lane == 0)
        out[(size_t)b * Odim + o] = s + bfc[o];
}

extern "C" void kernel_launch(void* const* d_in, const int* in_sizes, int n_in,
                              void* d_out, int out_size)
{
    const float* x   = (const float*)d_in[0];
    const float* Wih = (const float*)d_in[1];
    const float* Whh = (const float*)d_in[2];
    const float* bih = (const float*)d_in[3];
    const float* bhh = (const float*)d_in[4];
    const float* Wfc = (const float*)d_in[5];
    const float* bfc = (const float*)d_in[6];
    float* out = (float*)d_out;

    cudaFuncSetAttribute(lstm_persistent,
                         cudaFuncAttributeMaxDynamicSharedMemorySize, SMEM_DYN);

    zero_hb<<<512, 1024>>>();
    prep_x<<<16384, 1024>>>(x);
    prep_weights<<<16384, 1024>>>(Wih, Whh);
    lstm_persistent<<<NBLK, NTHR, SMEM_DYN>>>(bih, bhh);
    fc_kernel<<<(Bsz * Odim) / 8, 256>>>(Wfc, bfc, out);
}

// round 15
// speedup vs baseline: 1.7132x; 1.4407x over previous
#include <cuda_runtime.h>
#include <cuda_fp16.h>
#include <stdint.h>
#include <math.h>

#define Bsz  64
#define Tlen 256
#define Hdim 1024
#define Lnum 4
#define Odim 512
#define NBLK 128
#define NTHR 512
#define NCHUNK 16
#define NSTEP (Tlen + Lnum - 1)    // 259 wavefront steps
#define ASTR 272                   // A smem row pitch bytes
#define AHALF 17408u               // 64 rows * 272
#define ASLOT 34816u               // A hi+lo per chunk

// ---- persistent device state ----
// W (single fp16) in MMA B-fragment order:
// per (l,nb): [ck 16][kkg 8][nt 4][lane 32][j 4][reg 2] uint32 = 512 KB
__device__ __align__(16) unsigned g_Wf[(size_t)Lnum * 32 * 131072];    // 64 MB
__device__ __align__(16) __half g_xb_hi[(size_t)Tlen * 8 * 64 * 128];  // 32 MB
__device__ __align__(16) __half g_xb_lo[(size_t)Tlen * 8 * 64 * 128];  // 32 MB
__device__ __align__(16) __half g_hb_hi[Lnum * 2 * 8 * 64 * 128];      // 1 MB
__device__ __align__(16) __half g_hb_lo[Lnum * 2 * 8 * 64 * 128];      // 1 MB
__device__ float g_hfin[Bsz * Hdim];

__device__ volatile unsigned g_gen = 0;
__device__ unsigned g_count = 0;

__device__ __forceinline__ void grid_sync() {
    __syncthreads();
    if (threadIdx.x == 0) {
        __threadfence();
        unsigned my = g_gen;
        if (atomicAdd(&g_count, 1u) == NBLK - 1) {
            g_count = 0; __threadfence(); g_gen = my + 1;
        } else {
            while (g_gen == my) { __nanosleep(20); }
        }
        __threadfence();
    }
    __syncthreads();
}

__device__ __forceinline__ uint32_t smem_u32(const void* p) {
    uint32_t a;
    asm("{ .reg .u64 t; cvta.to.shared.u64 t, %1; cvt.u32.u64 %0, t; }"
        : "=r"(a) : "l"(p));
    return a;
}
__device__ __forceinline__ float ex2f(float x) {
    float r; asm("ex2.approx.f32 %0, %1;" : "=f"(r) : "f"(x)); return r;
}
__device__ __forceinline__ float rcpf(float x) {
    float r; asm("rcp.approx.f32 %0, %1;" : "=f"(r) : "f"(x)); return r;
}
__device__ __forceinline__ float sigf(float x) {
    return rcpf(1.0f + ex2f(-1.4426950408889634f * x));
}
__device__ __forceinline__ float tanhfast(float x) {
    float e = ex2f(2.8853900817779268f * x);
    return 1.0f - 2.0f * rcpf(e + 1.0f);
}

#define LDSM4(r, a)                                                           \
    asm volatile("ldmatrix.sync.aligned.m8n8.x4.shared.b16 {%0,%1,%2,%3}, [%4];" \
        : "=r"((r)[0]), "=r"((r)[1]), "=r"((r)[2]), "=r"((r)[3]) : "r"(a))

#define MMA(d, a, b0, b1)                                                     \
    asm volatile("mma.sync.aligned.m16n8k16.row.col.f32.f16.f16.f32 "         \
        "{%0,%1,%2,%3},{%4,%5,%6,%7},{%8,%9},{%0,%1,%2,%3};"                  \
        : "+f"((d)[0]), "+f"((d)[1]), "+f"((d)[2]), "+f"((d)[3])              \
        : "r"((a)[0]), "r"((a)[1]), "r"((a)[2]), "r"((a)[3]),                 \
          "r"(b0), "r"(b1))

#define LDG128CG(q, p)                                                        \
    asm volatile("ld.global.cg.v4.u32 {%0,%1,%2,%3}, [%4];"                   \
        : "=r"((q).x), "=r"((q).y), "=r"((q).z), "=r"((q).w)                  \
        : "l"(p))

#define CPA16(dst, src) \
    asm volatile("cp.async.ca.shared.global [%0], [%1], 16;" :: "r"(dst), "l"(src))
#define CPA_COMMIT() asm volatile("cp.async.commit_group;" ::: "memory")
#define CPA_WAIT(n)  asm volatile("cp.async.wait_group %0;" :: "n"(n) : "memory")

// smem: bias[128] | c[64][32] | 4 A slots
#define OFF_BIAS 0
#define OFF_C    512
#define OFF_A    8704
#define SMEM_DYN (8704 + 4 * 34816)      // 147968

__global__ void zero_hb() {
    int i = blockIdx.x * 1024 + threadIdx.x;      // grid 512
    g_hb_hi[i] = __float2half(0.f);
    g_hb_lo[i] = __float2half(0.f);
}

__global__ void prep_x(const float* __restrict__ x) {
    size_t idx = (size_t)blockIdx.x * 1024 + threadIdx.x;   // 2^24
    int c  = (int)(idx & 127);
    int b  = (int)((idx >> 7) & 63);
    int ck = (int)((idx >> 13) & 7);
    int t  = (int)(idx >> 16);
    float v = x[((size_t)b * Tlen + t) * 1024 + ck * 128 + c];
    __half h = __float2half(v);
    size_t dst = (((size_t)(t * 8 + ck)) * 64 + b) * 128 + c;
    g_xb_hi[dst] = h;
    g_xb_lo[dst] = __float2half(v - __half2float(h));
}

// Write W (single fp16) in MMA B-fragment order. One thread per uint32.
__global__ void prep_weights(const float* __restrict__ Wih,
                             const float* __restrict__ Whh) {
    unsigned idx = blockIdx.x * 1024 + threadIdx.x;   // 2^24
    int reg  = idx & 1;
    int j    = (idx >> 1) & 3;
    int lane = (idx >> 3) & 31;
    int nt   = (idx >> 8) & 3;
    int kkg  = (idx >> 10) & 7;
    int ck   = (idx >> 13) & 15;
    int nb   = (idx >> 17) & 31;
    int l    = (idx >> 22) & 3;

    int n_local = nt * 32 + j * 8 + (lane >> 2);          // 0..127 gate col
    int k_local = kkg * 16 + (lane & 3) * 2 + reg * 8;    // even k
    int gate = n_local >> 5, hid = nb * 32 + (n_local & 31);
    size_t grow = (size_t)l * 4096 * 1024 + (size_t)(gate * 1024 + hid) * 1024;
    int k0 = ck * 128 + k_local;

    float v0 = (k0 < 1024)     ? Wih[grow + k0]     : Whh[grow + k0 - 1024];
    float v1 = (k0 + 1 < 1024) ? Wih[grow + k0 + 1] : Whh[grow + k0 + 1 - 1024];
    union { __half2 b; unsigned u; } q;
    q.b = __halves2half2(__float2half(v0), __float2half(v1));

    size_t off = ((size_t)l * 32 + nb) * 131072
               + (size_t)((((ck * 8 + kkg) * 4 + nt) * 32 + lane) * 8 + j * 2 + reg);
    g_Wf[off] = q.u;
}

__global__ __launch_bounds__(NTHR, 1) void lstm_persistent(
    const float* __restrict__ bih, const float* __restrict__ bhh)
{
    extern __shared__ char sm[];
    const uint32_t sbase = smem_u32(sm);

    const int tid  = threadIdx.x;
    const int wid  = tid >> 5;
    const int lane = tid & 31;
    const int bx   = blockIdx.x;
    const int L    = bx >> 5;
    const int nb   = bx & 31;
    const int n0   = nb * 32;
    // 16 warps = 2m(32) x 4n(32) x 2kg(4 k-steps)
    const int mt = wid & 1;
    const int nt = (wid >> 1) & 3;
    const int kg = wid >> 3;

    if (tid < 128) {
        int gate = tid >> 5, hid = n0 + (tid & 31);
        int row = L * 4096 + gate * 1024 + hid;
        ((float*)(sm + OFF_BIAS))[tid] = bih[row] + bhh[row];
    }
    float* csm = (float*)(sm + OFF_C);   // [64][32]
    #pragma unroll
    for (int i = 0; i < 4; ++i)
        csm[i * NTHR + tid] = 0.f;
    __syncthreads();

    // A ldmatrix per-lane offsets (m32 per warp: two m16 frags)
    const uint32_t a_off0 = (uint32_t)(mt * 32 + (lane & 15)) * ASTR
                          + ((uint32_t)(lane >> 4) << 4);
    const uint32_t a_off1 = a_off0 + 16u * ASTR;
    // A cp.async dest offsets (512 thr: 2 x 16B per half)
    uint32_t ado[2];
    #pragma unroll
    for (int i = 0; i < 2; ++i) {
        int u = i * 512 + tid;
        ado[i] = (uint32_t)(u >> 4) * ASTR + (uint32_t)(u & 15) * 16;
    }
    const uint32_t kb0 = (uint32_t)kg * 128;   // byte offset of first k-step

    const char* wT = (const char*)(g_Wf + ((size_t)L * 32 + nb) * 131072);
    // B fragment byte offset for (ck, kk in 0..3)
    #define BOFF(ck, kk) ((size_t)((((ck) * 8 + kg * 4 + (kk)) * 4 + nt) << 10) \
                          + (size_t)lane * 32)

    for (int s = 0; s < NSTEP; ++s) {
        const int t = s - L;
        if (0 <= t && t < Tlen) {
            const int par = t & 1;
            const char *blHi, *blLo;
            if (L == 0) {
                blHi = (const char*)(g_xb_hi + (size_t)t * 8 * 8192);
                blLo = (const char*)(g_xb_lo + (size_t)t * 8 * 8192);
            } else {
                size_t o = (size_t)((L - 1) * 2 + par) * 8 * 8192;
                blHi = (const char*)(g_hb_hi + o);
                blLo = (const char*)(g_hb_lo + o);
            }
            size_t oh = (size_t)(L * 2 + (par ^ 1)) * 8 * 8192;
            const char* bhHi = (const char*)(g_hb_hi + oh);
            const char* bhLo = (const char*)(g_hb_lo + oh);

            float acc0[4][4] = {}, acc1[4][4] = {};   // [m-frag][n-frag][4]

            #define SRC_A_HI(ck) (((ck) < 8) ? blHi + (size_t)(ck) * 16384    \
                                             : bhHi + (size_t)((ck) - 8) * 16384)
            #define SRC_A_LO(ck) (((ck) < 8) ? blLo + (size_t)(ck) * 16384    \
                                             : bhLo + (size_t)((ck) - 8) * 16384)
            #define ISSUE_A(ck, slot) do {                                    \
                uint32_t aB = sbase + OFF_A + (uint32_t)(slot) * ASLOT;       \
                _Pragma("unroll")                                             \
                for (int i_ = 0; i_ < 2; ++i_) {                              \
                    CPA16(aB + ado[i_],                                       \
                          SRC_A_HI(ck) + (size_t)(i_ * 512 + tid) * 16);      \
                    CPA16(aB + AHALF + ado[i_],                               \
                          SRC_A_LO(ck) + (size_t)(i_ * 512 + tid) * 16);      \
                }                                                             \
            } while (0)

            // prologue: 3 A chunks in flight
            ISSUE_A(0, 0); CPA_COMMIT();
            ISSUE_A(1, 1); CPA_COMMIT();
            ISSUE_A(2, 2); CPA_COMMIT();

            // B pipeline: load (0,0) fragments (hi only)
            uint4 qh0, qh1;
            {
                size_t o = BOFF(0, 0);
                LDG128CG(qh0, (const uint4*)(wT + o));
                LDG128CG(qh1, (const uint4*)(wT + o + 16));
            }

            for (int ck = 0; ck < NCHUNK; ++ck) {
                const int slot = ck & 3;
                if (ck <= 13)      CPA_WAIT(2);   // group(ck) landed
                else if (ck == 14) CPA_WAIT(1);
                else               CPA_WAIT(0);
                __syncthreads();                  // visibility + slot reuse
                if (ck + 3 < NCHUNK) {
                    ISSUE_A(ck + 3, (ck + 3) & 3);
                    CPA_COMMIT();
                }

                const uint32_t aH = sbase + OFF_A + (uint32_t)slot * ASLOT;
                const uint32_t aL = aH + AHALF;
                #pragma unroll
                for (int kk = 0; kk < 4; ++kk) {
                    uint4 nh0, nh1;
                    const bool last = (ck == NCHUNK - 1) && (kk == 3);
                    if (!last) {
                        int nck = (kk == 3) ? ck + 1 : ck;
                        int nkk = (kk == 3) ? 0 : kk + 1;
                        size_t o = BOFF(nck, nkk);
                        LDG128CG(nh0, (const uint4*)(wT + o));
                        LDG128CG(nh1, (const uint4*)(wT + o + 16));
                    }
                    const uint32_t kb = kb0 + (uint32_t)kk * 32;
                    uint32_t ah0[4], ah1[4], al0[4], al1[4];
                    LDSM4(ah0, aH + a_off0 + kb);
                    LDSM4(ah1, aH + a_off1 + kb);
                    LDSM4(al0, aL + a_off0 + kb);
                    LDSM4(al1, aL + a_off1 + kb);
                    // pass 1: Ahi * W
                    MMA(acc0[0], ah0, qh0.x, qh0.y);
                    MMA(acc0[1], ah0, qh0.z, qh0.w);
                    MMA(acc0[2], ah0, qh1.x, qh1.y);
                    MMA(acc0[3], ah0, qh1.z, qh1.w);
                    MMA(acc1[0], ah1, qh0.x, qh0.y);
                    MMA(acc1[1], ah1, qh0.z, qh0.w);
                    MMA(acc1[2], ah1, qh1.x, qh1.y);
                    MMA(acc1[3], ah1, qh1.z, qh1.w);
                    // pass 2: Alo * W
                    MMA(acc0[0], al0, qh0.x, qh0.y);
                    MMA(acc0[1], al0, qh0.z, qh0.w);
                    MMA(acc0[2], al0, qh1.x, qh1.y);
                    MMA(acc0[3], al0, qh1.z, qh1.w);
                    MMA(acc1[0], al1, qh0.x, qh0.y);
                    MMA(acc1[1], al1, qh0.z, qh0.w);
                    MMA(acc1[2], al1, qh1.x, qh1.y);
                    MMA(acc1[3], al1, qh1.z, qh1.w);
                    if (!last) { qh0 = nh0; qh1 = nh1; }
                }
            }
            #undef ISSUE_A
            #undef SRC_A_HI
            #undef SRC_A_LO

            // epilogue: Gs[2][64][132] = 67584 B, fits in A slots 0-1 region.
            // Safe without a barrier: lagging warps read slots 2/3 only.
            float* Gs = (float*)(sm + OFF_A);
            #pragma unroll
            for (int mi = 0; mi < 2; ++mi) {
                float (*am)[4] = mi ? acc1 : acc0;
                #pragma unroll
                for (int ni = 0; ni < 4; ++ni) {
                    int R = mt * 32 + mi * 16 + (lane >> 2);
                    int C = nt * 32 + ni * 8 + (lane & 3) * 2;
                    int base = (kg * 64 + R) * 132 + C;
                    Gs[base]               = am[ni][0];
                    Gs[base + 1]           = am[ni][1];
                    Gs[base + 8 * 132]     = am[ni][2];
                    Gs[base + 8 * 132 + 1] = am[ni][3];
                }
            }
            __syncthreads();

            {
                const float* bias = (const float*)(sm + OFF_BIAS);
                const int ckd = nb >> 2;
                #pragma unroll
                for (int q = 0; q < 4; ++q) {
                    int e = q * 512 + tid;          // 0..2047
                    int b = e >> 5, hl = e & 31;
                    float gi = Gs[b * 132 + hl]      + Gs[(64 + b) * 132 + hl]
                             + bias[hl];
                    float gf = Gs[b * 132 + 32 + hl] + Gs[(64 + b) * 132 + 32 + hl]
                             + bias[32 + hl];
                    float gg = Gs[b * 132 + 64 + hl] + Gs[(64 + b) * 132 + 64 + hl]
                             + bias[64 + hl];
                    float go = Gs[b * 132 + 96 + hl] + Gs[(64 + b) * 132 + 96 + hl]
                             + bias[96 + hl];
                    float ig = sigf(gi), fg = sigf(gf), og = sigf(go);
                    float gt = tanhfast(gg);
                    float* cp_ = csm + b * 32 + hl;
                    float cn = fg * (*cp_) + ig * gt;
                    *cp_ = cn;
                    float hn = og * tanhfast(cn);
                    __half hh = __float2half(hn);
                    __half hlw = __float2half(hn - __half2float(hh));
                    int coltile = (nb & 3) * 32 + hl;
                    size_t off = ((((size_t)(L * 2 + par) * 8 + ckd) * 64 + b) * 128)
                               + coltile;
                    g_hb_hi[off] = hh;
                    g_hb_lo[off] = hlw;
                    if (t == Tlen - 1 && L == Lnum - 1)
                        g_hfin[(size_t)b * Hdim + n0 + hl] = hn;
                }
            }
        }
        grid_sync();
    }
    #undef BOFF
}

__global__ void fc_kernel(const float* __restrict__ Wfc,
                          const float* __restrict__ bfc,
                          float* __restrict__ out)
{
    const float* h = g_hfin;
    int warp = (blockIdx.x * blockDim.x + threadIdx.x) >> 5;
    int lane = threadIdx.x & 31;
    int b = warp >> 9;
    int o = warp & (Odim - 1);
    const float4* hv = (const float4*)(h   + (size_t)b * Hdim);
    const float4* wv = (const float4*)(Wfc + (size_t)o * Hdim);
    float s = 0.f;
    #pragma unroll
    for (int it = 0; it < 8; ++it) {
        float4 a = hv[it * 32 + lane];
        float4 w = wv[it * 32 + lane];
        s += a.x * w.x + a.y * w.y + a.z * w.z + a.w * w.w;
    }
    #pragma unroll
    for (int off = 16; off; off >>= 1)
        s += __shfl_xor_sync(0xffffffffu, s, off);
    if (lane == 0)
        out[(size_t)b * Odim + o] = s + bfc[o];
}

extern "C" void kernel_launch(void* const* d_in, const int* in_sizes, int n_in,
                              void* d_out, int out_size)
{
    const float* x   = (const float*)d_in[0];
    const float* Wih = (const float*)d_in[1];
    const float* Whh = (const float*)d_in[2];
    const float* bih = (const float*)d_in[3];
    const float* bhh = (const float*)d_in[4];
    const float* Wfc = (const float*)d_in[5];
    const float* bfc = (const float*)d_in[6];
    float* out = (float*)d_out;

    cudaFuncSetAttribute(lstm_persistent,
                         cudaFuncAttributeMaxDynamicSharedMemorySize, SMEM_DYN);

    zero_hb<<<512, 1024>>>();
    prep_x<<<16384, 1024>>>(x);
    prep_weights<<<16384, 1024>>>(Wih, Whh);
    lstm_persistent<<<NBLK, NTHR, SMEM_DYN>>>(bih, bhh);
    fc_kernel<<<(Bsz * Odim) / 8, 256>>>(Wfc, bfc, out);
}

// round 16
// speedup vs baseline: 2.1635x; 1.2629x over previous
#include <cuda_runtime.h>
#include <cuda_fp16.h>
#include <stdint.h>
#include <math.h>

#define Bsz  64
#define Tlen 256
#define Hdim 1024
#define Lnum 4
#define Odim 512
#define NBLK 128
#define NTHR 512
#define NCHUNK 16
#define NSTEP (Tlen + Lnum - 1)    // 259 wavefront steps

// ---- persistent device state ----
// W (fp16) in MMA B-fragment order: per (l,nb) 512 KB (layout from R13/14)
__device__ __align__(16) unsigned g_Wf[(size_t)Lnum * 32 * 131072];    // 64 MB
// x and h in MMA A-fragment order:
// per (t | L,par): [ck 8][kkg 8][m16 4][lane 32][reg 4] uint32 = 128 KB
__device__ __align__(16) __half g_xa_hi[(size_t)Tlen * 65536];         // 32 MB
__device__ __align__(16) __half g_xa_lo[(size_t)Tlen * 65536];         // 32 MB
__device__ __align__(16) __half g_ha_hi[Lnum * 2 * 65536];             // 1 MB
__device__ __align__(16) __half g_ha_lo[Lnum * 2 * 65536];             // 1 MB
__device__ float g_hfin[Bsz * Hdim];

__device__ volatile unsigned g_gen = 0;
__device__ unsigned g_count = 0;

__device__ __forceinline__ void grid_sync() {
    __syncthreads();
    if (threadIdx.x == 0) {
        __threadfence();                 // also CCTL.IVALL -> L1D invalidate
        unsigned my = g_gen;
        if (atomicAdd(&g_count, 1u) == NBLK - 1) {
            g_count = 0; __threadfence(); g_gen = my + 1;
        } else {
            while (g_gen == my) { __nanosleep(20); }
        }
        __threadfence();
    }
    __syncthreads();
}

__device__ __forceinline__ uint32_t smem_u32(const void* p) {
    uint32_t a;
    asm("{ .reg .u64 t; cvta.to.shared.u64 t, %1; cvt.u32.u64 %0, t; }"
        : "=r"(a) : "l"(p));
    return a;
}
__device__ __forceinline__ float ex2f(float x) {
    float r; asm("ex2.approx.f32 %0, %1;" : "=f"(r) : "f"(x)); return r;
}
__device__ __forceinline__ float rcpf(float x) {
    float r; asm("rcp.approx.f32 %0, %1;" : "=f"(r) : "f"(x)); return r;
}
__device__ __forceinline__ float sigf(float x) {
    return rcpf(1.0f + ex2f(-1.4426950408889634f * x));
}
__device__ __forceinline__ float tanhfast(float x) {
    float e = ex2f(2.8853900817779268f * x);
    return 1.0f - 2.0f * rcpf(e + 1.0f);
}

// MMA with A fragment held in a uint4
#define MMAQ(d, q, b0, b1)                                                    \
    asm volatile("mma.sync.aligned.m16n8k16.row.col.f32.f16.f16.f32 "         \
        "{%0,%1,%2,%3},{%4,%5,%6,%7},{%8,%9},{%0,%1,%2,%3};"                  \
        : "+f"((d)[0]), "+f"((d)[1]), "+f"((d)[2]), "+f"((d)[3])              \
        : "r"((q).x), "r"((q).y), "r"((q).z), "r"((q).w),                     \
          "r"(b0), "r"(b1))

#define LDG128CA(q, p)                                                        \
    asm volatile("ld.global.ca.v4.u32 {%0,%1,%2,%3}, [%4];"                   \
        : "=r"((q).x), "=r"((q).y), "=r"((q).z), "=r"((q).w)                  \
        : "l"(p))
#define LDG128CG(q, p)                                                        \
    asm volatile("ld.global.cg.v4.u32 {%0,%1,%2,%3}, [%4];"                   \
        : "=r"((q).x), "=r"((q).y), "=r"((q).z), "=r"((q).w)                  \
        : "l"(p))

// smem: bias[128] f32 | c[64][32] f32 | Gs[2][64][132] f32
#define OFF_BIAS 0
#define OFF_C    512
#define OFF_G    8704
#define SMEM_DYN (8704 + 2 * 64 * 132 * 4)    // 76288

// A-fragment halfword offset for element (row r16 in m16 tile, col K in k16)
__device__ __forceinline__ size_t afrag_off(int ckp, int kkg, int m16,
                                            int r, int K) {
    int lane = (r & 7) * 4 + ((K & 7) >> 1);
    int reg  = (r >> 3) + ((K >> 3) << 1);
    return ((((size_t)(ckp * 8 + kkg) * 4 + m16) * 32 + lane) * 4 + reg) * 2
           + (K & 1);
}

__global__ void zero_ha() {
    int i = blockIdx.x * 1024 + threadIdx.x;      // grid 512 -> 524288
    g_ha_hi[i] = __float2half(0.f);
    g_ha_lo[i] = __float2half(0.f);
}

__global__ void prep_x(const float* __restrict__ x) {
    unsigned idx = blockIdx.x * 1024 + threadIdx.x;   // 2^24
    int H = idx & 1023;
    int b = (idx >> 10) & 63;
    int t = idx >> 16;
    float v = x[((size_t)b * Tlen + t) * 1024 + H];
    __half h = __float2half(v);
    size_t off = (size_t)t * 65536
               + afrag_off(H >> 7, (H >> 4) & 7, b >> 4, b & 15, H & 15);
    g_xa_hi[off] = h;
    g_xa_lo[off] = __float2half(v - __half2float(h));
}

// W (single fp16) in MMA B-fragment order (validated layout).
__global__ void prep_weights(const float* __restrict__ Wih,
                             const float* __restrict__ Whh) {
    unsigned idx = blockIdx.x * 1024 + threadIdx.x;   // 2^24
    int reg  = idx & 1;
    int j    = (idx >> 1) & 3;
    int lane = (idx >> 3) & 31;
    int nt   = (idx >> 8) & 3;
    int kkg  = (idx >> 10) & 7;
    int ck   = (idx >> 13) & 15;
    int nb   = (idx >> 17) & 31;
    int l    = (idx >> 22) & 3;

    int n_local = nt * 32 + j * 8 + (lane >> 2);
    int k_local = kkg * 16 + (lane & 3) * 2 + reg * 8;
    int gate = n_local >> 5, hid = nb * 32 + (n_local & 31);
    size_t grow = (size_t)l * 4096 * 1024 + (size_t)(gate * 1024 + hid) * 1024;
    int k0 = ck * 128 + k_local;

    float v0 = (k0 < 1024)     ? Wih[grow + k0]     : Whh[grow + k0 - 1024];
    float v1 = (k0 + 1 < 1024) ? Wih[grow + k0 + 1] : Whh[grow + k0 + 1 - 1024];
    union { __half2 b; unsigned u; } q;
    q.b = __halves2half2(__float2half(v0), __float2half(v1));

    size_t off = ((size_t)l * 32 + nb) * 131072
               + (size_t)((((ck * 8 + kkg) * 4 + nt) * 32 + lane) * 8 + j * 2 + reg);
    g_Wf[off] = q.u;
}

__global__ __launch_bounds__(NTHR, 1) void lstm_persistent(
    const float* __restrict__ bih, const float* __restrict__ bhh)
{
    extern __shared__ char sm[];

    const int tid  = threadIdx.x;
    const int wid  = tid >> 5;
    const int lane = tid & 31;
    const int bx   = blockIdx.x;
    const int L    = bx >> 5;
    const int nb   = bx & 31;
    const int n0   = nb * 32;
    // 16 warps = 2m(32) x 4n(32) x 2kg(4 k-steps)
    const int mt = wid & 1;
    const int nt = (wid >> 1) & 3;
    const int kg = wid >> 3;

    if (tid < 128) {
        int gate = tid >> 5, hid = n0 + (tid & 31);
        int row = L * 4096 + gate * 1024 + hid;
        ((float*)(sm + OFF_BIAS))[tid] = bih[row] + bhh[row];
    }
    float* csm = (float*)(sm + OFF_C);   // [64][32]
    #pragma unroll
    for (int i = 0; i < 4; ++i)
        csm[i * NTHR + tid] = 0.f;
    __syncthreads();

    // per-warp A byte offset within a chunk (mi=0; +512 for mi=1)
    const uint32_t awoff = (uint32_t)(kg * 4) * 2048u + (uint32_t)mt * 1024u
                         + (uint32_t)lane * 16u;
    const char* wT = (const char*)(g_Wf + ((size_t)L * 32 + nb) * 131072);
    #define BOFF(ck, kk) ((size_t)((((ck) * 8 + kg * 4 + (kk)) * 4 + nt) << 10) \
                          + (size_t)lane * 32)

    for (int s = 0; s < NSTEP; ++s) {
        const int t = s - L;
        if (0 <= t && t < Tlen) {
            const int par = t & 1;
            // A sources (fragment layout): chunks 0-7 input, 8-15 own h_{t-1}
            const char *inHi, *inLo;
            if (L == 0) {
                inHi = (const char*)(g_xa_hi + (size_t)t * 65536);
                inLo = (const char*)(g_xa_lo + (size_t)t * 65536);
            } else {
                size_t o = (size_t)((L - 1) * 2 + par) * 65536;
                inHi = (const char*)(g_ha_hi + o);
                inLo = (const char*)(g_ha_lo + o);
            }
            size_t oh = (size_t)(L * 2 + (par ^ 1)) * 65536;
            const char* ownHi = (const char*)(g_ha_hi + oh);
            const char* ownLo = (const char*)(g_ha_lo + oh);

            float acc0[4][4] = {}, acc1[4][4] = {};

            #define ALOAD(ck, kk, h0, h1, l0, l1) do {                        \
                const char* bh_ = ((ck) < 8) ? inHi + (size_t)(ck) * 16384    \
                                             : ownHi + (size_t)((ck) - 8) * 16384; \
                const char* bl_ = ((ck) < 8) ? inLo + (size_t)(ck) * 16384    \
                                             : ownLo + (size_t)((ck) - 8) * 16384; \
                uint32_t o_ = awoff + (uint32_t)(kk) * 2048u;                 \
                LDG128CA(h0, bh_ + o_);                                       \
                LDG128CA(h1, bh_ + o_ + 512u);                                \
                LDG128CA(l0, bl_ + o_);                                       \
                LDG128CA(l1, bl_ + o_ + 512u);                                \
            } while (0)
            #define BLOAD(ck, kk, b0, b1) do {                                \
                size_t o_ = BOFF(ck, kk);                                     \
                LDG128CG(b0, wT + o_);                                        \
                LDG128CG(b1, wT + o_ + 16);                                   \
            } while (0)

            uint4 ch0, ch1, cl0, cl1, cb0, cb1;
            ALOAD(0, 0, ch0, ch1, cl0, cl1);
            BLOAD(0, 0, cb0, cb1);

            for (int ck = 0; ck < NCHUNK; ++ck) {
                #pragma unroll
                for (int kk = 0; kk < 4; ++kk) {
                    uint4 nh0, nh1, nl0, nl1, nb0, nb1;
                    const bool last = (ck == NCHUNK - 1) && (kk == 3);
                    if (!last) {
                        int nck = (kk == 3) ? ck + 1 : ck;
                        int nkk = (kk == 3) ? 0 : kk + 1;
                        ALOAD(nck, nkk, nh0, nh1, nl0, nl1);
                        BLOAD(nck, nkk, nb0, nb1);
                    }
                    // hi pass
                    MMAQ(acc0[0], ch0, cb0.x, cb0.y);
                    MMAQ(acc0[1], ch0, cb0.z, cb0.w);
                    MMAQ(acc0[2], ch0, cb1.x, cb1.y);
                    MMAQ(acc0[3], ch0, cb1.z, cb1.w);
                    MMAQ(acc1[0], ch1, cb0.x, cb0.y);
                    MMAQ(acc1[1], ch1, cb0.z, cb0.w);
                    MMAQ(acc1[2], ch1, cb1.x, cb1.y);
                    MMAQ(acc1[3], ch1, cb1.z, cb1.w);
                    // lo pass
                    MMAQ(acc0[0], cl0, cb0.x, cb0.y);
                    MMAQ(acc0[1], cl0, cb0.z, cb0.w);
                    MMAQ(acc0[2], cl0, cb1.x, cb1.y);
                    MMAQ(acc0[3], cl0, cb1.z, cb1.w);
                    MMAQ(acc1[0], cl1, cb0.x, cb0.y);
                    MMAQ(acc1[1], cl1, cb0.z, cb0.w);
                    MMAQ(acc1[2], cl1, cb1.x, cb1.y);
                    MMAQ(acc1[3], cl1, cb1.z, cb1.w);
                    if (!last) {
                        ch0 = nh0; ch1 = nh1; cl0 = nl0; cl1 = nl1;
                        cb0 = nb0; cb1 = nb1;
                    }
                }
            }
            #undef ALOAD
            #undef BLOAD

            // epilogue: partial gates per k-group into dedicated smem
            float* Gs = (float*)(sm + OFF_G);   // [2][64][132]
            #pragma unroll
            for (int mi = 0; mi < 2; ++mi) {
                float (*am)[4] = mi ? acc1 : acc0;
                #pragma unroll
                for (int ni = 0; ni < 4; ++ni) {
                    int R = mt * 32 + mi * 16 + (lane >> 2);
                    int C = nt * 32 + ni * 8 + (lane & 3) * 2;
                    int base = (kg * 64 + R) * 132 + C;
                    Gs[base]               = am[ni][0];
                    Gs[base + 1]           = am[ni][1];
                    Gs[base + 8 * 132]     = am[ni][2];
                    Gs[base + 8 * 132 + 1] = am[ni][3];
                }
            }
            __syncthreads();

            {
                const float* bias = (const float*)(sm + OFF_BIAS);
                __half* dstHi = (__half*)g_ha_hi + (size_t)(L * 2 + par) * 65536;
                __half* dstLo = (__half*)g_ha_lo + (size_t)(L * 2 + par) * 65536;
                #pragma unroll
                for (int q = 0; q < 4; ++q) {
                    int e = q * 512 + tid;          // 0..2047
                    int b = e >> 5, hl = e & 31;
                    float gi = Gs[b * 132 + hl]      + Gs[(64 + b) * 132 + hl]
                             + bias[hl];
                    float gf = Gs[b * 132 + 32 + hl] + Gs[(64 + b) * 132 + 32 + hl]
                             + bias[32 + hl];
                    float gg = Gs[b * 132 + 64 + hl] + Gs[(64 + b) * 132 + 64 + hl]
                             + bias[64 + hl];
                    float go = Gs[b * 132 + 96 + hl] + Gs[(64 + b) * 132 + 96 + hl]
                             + bias[96 + hl];
                    float ig = sigf(gi), fg = sigf(gf), og = sigf(go);
                    float gt = tanhfast(gg);
                    float* cp_ = csm + b * 32 + hl;
                    float cn = fg * (*cp_) + ig * gt;
                    *cp_ = cn;
                    float hn = og * tanhfast(cn);
                    __half hh = __float2half(hn);
                    __half hlw = __float2half(hn - __half2float(hh));
                    int H = n0 + hl;                 // 0..1023
                    size_t off = afrag_off(H >> 7, (H >> 4) & 7,
                                           b >> 4, b & 15, H & 15);
                    dstHi[off] = hh;
                    dstLo[off] = hlw;
                    if (t == Tlen - 1 && L == Lnum - 1)
                        g_hfin[(size_t)b * Hdim + H] = hn;
                }
            }
        }
        grid_sync();   // orders h writes; IVALL kills stale L1 A lines
    }
    #undef BOFF
}

__global__ void fc_kernel(const float* __restrict__ Wfc,
                          const float* __restrict__ bfc,
                          float* __restrict__ out)
{
    const float* h = g_hfin;
    int warp = (blockIdx.x * blockDim.x + threadIdx.x) >> 5;
    int lane = threadIdx.x & 31;
    int b = warp >> 9;
    int o = warp & (Odim - 1);
    const float4* hv = (const float4*)(h   + (size_t)b * Hdim);
    const float4* wv = (const float4*)(Wfc + (size_t)o * Hdim);
    float s = 0.f;
    #pragma unroll
    for (int it = 0; it < 8; ++it) {
        float4 a = hv[it * 32 + lane];
        float4 w = wv[it * 32 + lane];
        s += a.x * w.x + a.y * w.y + a.z * w.z + a.w * w.w;
    }
    #pragma unroll
    for (int off = 16; off; off >>= 1)
        s += __shfl_xor_sync(0xffffffffu, s, off);
    if (lane == 0)
        out[(size_t)b * Odim + o] = s + bfc[o];
}

extern "C" void kernel_launch(void* const* d_in, const int* in_sizes, int n_in,
                              void* d_out, int out_size)
{
    const float* x   = (const float*)d_in[0];
    const float* Wih = (const float*)d_in[1];
    const float* Whh = (const float*)d_in[2];
    const float* bih = (const float*)d_in[3];
    const float* bhh = (const float*)d_in[4];
    const float* Wfc = (const float*)d_in[5];
    const float* bfc = (const float*)d_in[6];
    float* out = (float*)d_out;

    cudaFuncSetAttribute(lstm_persistent,
                         cudaFuncAttributeMaxDynamicSharedMemorySize, SMEM_DYN);

    zero_ha<<<512, 1024>>>();
    prep_x<<<16384, 1024>>>(x);
    prep_weights<<<16384, 1024>>>(Wih, Whh);
    lstm_persistent<<<NBLK, NTHR, SMEM_DYN>>>(bih, bhh);
    fc_kernel<<<(Bsz * Odim) / 8, 256>>>(Wfc, bfc, out);
}

// round 17
// speedup vs baseline: 3.2543x; 1.5042x over previous
#include <cuda_runtime.h>
#include <cuda_fp16.h>
#include <stdint.h>
#include <math.h>

#define Bsz  64
#define Tlen 256
#define Hdim 1024
#define Lnum 4
#define Odim 512
#define NBLK 128
#define NTHR 512
#define NSTEP (Tlen + Lnum - 1)    // 259 wavefront steps

// ---- persistent device state ----
// W (fp16) in MMA B-fragment order: per (l,nb) 512 KB (validated layout)
__device__ __align__(16) unsigned g_Wf[(size_t)Lnum * 32 * 131072];    // 64 MB
// x and h in MMA A-fragment order (single fp16):
// per (t | L,par): [ck 8][kkg 8][m16 4][lane 32][reg 4] uint32 = 128 KB
__device__ __align__(16) __half g_xa[(size_t)Tlen * 65536];            // 32 MB
__device__ __align__(16) __half g_ha[Lnum * 2 * 65536];                // 1 MB
__device__ float g_hfin[Bsz * Hdim];

__device__ volatile unsigned g_gen = 0;
__device__ unsigned g_count = 0;

__device__ __forceinline__ void grid_sync() {
    __syncthreads();
    if (threadIdx.x == 0) {
        __threadfence();                 // also flushes L1D (CCTL.IVALL)
        unsigned my = g_gen;
        if (atomicAdd(&g_count, 1u) == NBLK - 1) {
            g_count = 0; __threadfence(); g_gen = my + 1;
        } else {
            while (g_gen == my) { __nanosleep(20); }
        }
        __threadfence();
    }
    __syncthreads();
}

__device__ __forceinline__ float ex2f(float x) {
    float r; asm("ex2.approx.f32 %0, %1;" : "=f"(r) : "f"(x)); return r;
}
__device__ __forceinline__ float rcpf(float x) {
    float r; asm("rcp.approx.f32 %0, %1;" : "=f"(r) : "f"(x)); return r;
}
__device__ __forceinline__ float sigf(float x) {
    return rcpf(1.0f + ex2f(-1.4426950408889634f * x));
}
__device__ __forceinline__ float tanhfast(float x) {
    float e = ex2f(2.8853900817779268f * x);
    return 1.0f - 2.0f * rcpf(e + 1.0f);
}

#define MMAQ(d, q, b0, b1)                                                    \
    asm volatile("mma.sync.aligned.m16n8k16.row.col.f32.f16.f16.f32 "         \
        "{%0,%1,%2,%3},{%4,%5,%6,%7},{%8,%9},{%0,%1,%2,%3};"                  \
        : "+f"((d)[0]), "+f"((d)[1]), "+f"((d)[2]), "+f"((d)[3])              \
        : "r"((q).x), "r"((q).y), "r"((q).z), "r"((q).w),                     \
          "r"(b0), "r"(b1))

#define LDG128CA(q, p)                                                        \
    asm volatile("ld.global.ca.v4.u32 {%0,%1,%2,%3}, [%4];"                   \
        : "=r"((q).x), "=r"((q).y), "=r"((q).z), "=r"((q).w)                  \
        : "l"(p))
#define LDG128CG(q, p)                                                        \
    asm volatile("ld.global.cg.v4.u32 {%0,%1,%2,%3}, [%4];"                   \
        : "=r"((q).x), "=r"((q).y), "=r"((q).z), "=r"((q).w)                  \
        : "l"(p))

// smem: bias[128] f32 | c[64][32] f32 | Gs[2][64][132] f32
#define OFF_BIAS 0
#define OFF_C    512
#define OFF_G    8704
#define SMEM_DYN (8704 + 2 * 64 * 132 * 4)    // 76288

// A-fragment halfword offset for (chunk ckp, k16-group kkg, m16 tile, row r, col K)
__device__ __forceinline__ size_t afrag_off(int ckp, int kkg, int m16,
                                            int r, int K) {
    int lane = (r & 7) * 4 + ((K & 7) >> 1);
    int reg  = (r >> 3) + ((K >> 3) << 1);
    return ((((size_t)(ckp * 8 + kkg) * 4 + m16) * 32 + lane) * 4 + reg) * 2
           + (K & 1);
}

__global__ void zero_ha() {
    int i = blockIdx.x * 1024 + threadIdx.x;      // grid 512 -> 524288
    g_ha[i] = __float2half(0.f);
}

__global__ void prep_x(const float* __restrict__ x) {
    unsigned idx = blockIdx.x * 1024 + threadIdx.x;   // 2^24
    int H = idx & 1023;
    int b = (idx >> 10) & 63;
    int t = idx >> 16;
    float v = x[((size_t)b * Tlen + t) * 1024 + H];
    size_t off = (size_t)t * 65536
               + afrag_off(H >> 7, (H >> 4) & 7, b >> 4, b & 15, H & 15);
    g_xa[off] = __float2half(v);
}

// W (single fp16) in MMA B-fragment order (validated layout).
__global__ void prep_weights(const float* __restrict__ Wih,
                             const float* __restrict__ Whh) {
    unsigned idx = blockIdx.x * 1024 + threadIdx.x;   // 2^24
    int reg  = idx & 1;
    int j    = (idx >> 1) & 3;
    int lane = (idx >> 3) & 31;
    int nt   = (idx >> 8) & 3;
    int kkg  = (idx >> 10) & 7;
    int ck   = (idx >> 13) & 15;
    int nb   = (idx >> 17) & 31;
    int l    = (idx >> 22) & 3;

    int n_local = nt * 32 + j * 8 + (lane >> 2);
    int k_local = kkg * 16 + (lane & 3) * 2 + reg * 8;
    int gate = n_local >> 5, hid = nb * 32 + (n_local & 31);
    size_t grow = (size_t)l * 4096 * 1024 + (size_t)(gate * 1024 + hid) * 1024;
    int k0 = ck * 128 + k_local;

    float v0 = (k0 < 1024)     ? Wih[grow + k0]     : Whh[grow + k0 - 1024];
    float v1 = (k0 + 1 < 1024) ? Wih[grow + k0 + 1] : Whh[grow + k0 + 1 - 1024];
    union { __half2 b; unsigned u; } q;
    q.b = __halves2half2(__float2half(v0), __float2half(v1));

    size_t off = ((size_t)l * 32 + nb) * 131072
               + (size_t)((((ck * 8 + kkg) * 4 + nt) * 32 + lane) * 8 + j * 2 + reg);
    g_Wf[off] = q.u;
}

__global__ __launch_bounds__(NTHR, 1) void lstm_persistent(
    const float* __restrict__ bih, const float* __restrict__ bhh)
{
    extern __shared__ char sm[];

    const int tid  = threadIdx.x;
    const int wid  = tid >> 5;
    const int lane = tid & 31;
    const int bx   = blockIdx.x;
    const int L    = bx >> 5;
    const int nb   = bx & 31;
    const int n0   = nb * 32;
    // 16 warps = 2m(32) x 4n(32) x 2kg(4 of 8 k16-steps per chunk)
    const int mt = wid & 1;
    const int nt = (wid >> 1) & 3;
    const int kg = wid >> 3;

    if (tid < 128) {
        int gate = tid >> 5, hid = n0 + (tid & 31);
        int row = L * 4096 + gate * 1024 + hid;
        ((float*)(sm + OFF_BIAS))[tid] = bih[row] + bhh[row];
    }
    float* csm = (float*)(sm + OFF_C);   // [64][32]
    #pragma unroll
    for (int i = 0; i < 4; ++i)
        csm[i * NTHR + tid] = 0.f;
    __syncthreads();

    // per-warp A byte offset within a chunk (m-frag 0; +512 for m-frag 1)
    const uint32_t awoff = (uint32_t)(kg * 4) * 2048u + (uint32_t)mt * 1024u
                         + (uint32_t)lane * 16u;
    const char* wT = (const char*)(g_Wf + ((size_t)L * 32 + nb) * 131072);
    #define BOFF(ck, kk) ((size_t)((((ck) * 8 + kg * 4 + (kk)) * 4 + nt) << 10) \
                          + (size_t)lane * 32)

    for (int s = 0; s < NSTEP; ++s) {
        const int t = s - L;
        if (0 <= t && t < Tlen) {
            const int par = t & 1;
            // A sources (fragment layout): chunks 0-7 input, 8-15 own h_{t-1}
            const char* inA;
            if (L == 0) inA = (const char*)(g_xa + (size_t)t * 65536);
            else        inA = (const char*)(g_ha
                              + (size_t)((L - 1) * 2 + par) * 65536);
            const char* ownA = (const char*)(g_ha
                              + (size_t)(L * 2 + (par ^ 1)) * 65536);

            float acc0[4][4] = {}, acc1[4][4] = {};

            // 4-slot operand ring over 64 global k-steps (ck = j>>2, kk = j&3)
            uint4 qa0[4], qa1[4], qb0[4], qb1[4];
            #define ALOADJ(j, sl) do {                                        \
                int ck_ = (j) >> 2, kk_ = (j) & 3;                            \
                const char* ba_ = (ck_ < 8) ? inA + (size_t)ck_ * 16384       \
                                  : ownA + (size_t)(ck_ - 8) * 16384;         \
                uint32_t o_ = awoff + (uint32_t)kk_ * 2048u;                  \
                LDG128CA(qa0[sl], ba_ + o_);                                  \
                LDG128CA(qa1[sl], ba_ + o_ + 512u);                           \
            } while (0)
            #define BLOADJ(j, sl) do {                                        \
                int ck_ = (j) >> 2, kk_ = (j) & 3;                            \
                size_t o_ = BOFF(ck_, kk_);                                   \
                LDG128CG(qb0[sl], wT + o_);                                   \
                LDG128CG(qb1[sl], wT + o_ + 16);                              \
            } while (0)

            ALOADJ(0, 0); BLOADJ(0, 0);
            ALOADJ(1, 1); BLOADJ(1, 1);
            ALOADJ(2, 2); BLOADJ(2, 2);

            for (int jo = 0; jo < 64; jo += 4) {
                #pragma unroll
                for (int ji = 0; ji < 4; ++ji) {
                    const int j = jo + ji;
                    const int sl = j & 3;
                    if (j + 3 < 64) {
                        const int jn = j + 3, sn = (j + 3) & 3;
                        ALOADJ(jn, sn);
                        BLOADJ(jn, sn);
                    }
                    MMAQ(acc0[0], qa0[sl], qb0[sl].x, qb0[sl].y);
                    MMAQ(acc0[1], qa0[sl], qb0[sl].z, qb0[sl].w);
                    MMAQ(acc0[2], qa0[sl], qb1[sl].x, qb1[sl].y);
                    MMAQ(acc0[3], qa0[sl], qb1[sl].z, qb1[sl].w);
                    MMAQ(acc1[0], qa1[sl], qb0[sl].x, qb0[sl].y);
                    MMAQ(acc1[1], qa1[sl], qb0[sl].z, qb0[sl].w);
                    MMAQ(acc1[2], qa1[sl], qb1[sl].x, qb1[sl].y);
                    MMAQ(acc1[3], qa1[sl], qb1[sl].z, qb1[sl].w);
                }
            }
            #undef ALOADJ
            #undef BLOADJ

            // epilogue: partial gates per k-group into dedicated smem
            float* Gs = (float*)(sm + OFF_G);   // [2][64][132]
            #pragma unroll
            for (int mi = 0; mi < 2; ++mi) {
                float (*am)[4] = mi ? acc1 : acc0;
                #pragma unroll
                for (int ni = 0; ni < 4; ++ni) {
                    int R = mt * 32 + mi * 16 + (lane >> 2);
                    int C = nt * 32 + ni * 8 + (lane & 3) * 2;
                    int base = (kg * 64 + R) * 132 + C;
                    Gs[base]               = am[ni][0];
                    Gs[base + 1]           = am[ni][1];
                    Gs[base + 8 * 132]     = am[ni][2];
                    Gs[base + 8 * 132 + 1] = am[ni][3];
                }
            }
            __syncthreads();

            {
                const float* bias = (const float*)(sm + OFF_BIAS);
                __half* dstA = (__half*)g_ha + (size_t)(L * 2 + par) * 65536;
                #pragma unroll
                for (int q = 0; q < 4; ++q) {
                    int e = q * 512 + tid;          // 0..2047
                    int b = e >> 5, hl = e & 31;
                    float gi = Gs[b * 132 + hl]      + Gs[(64 + b) * 132 + hl]
                             + bias[hl];
                    float gf = Gs[b * 132 + 32 + hl] + Gs[(64 + b) * 132 + 32 + hl]
                             + bias[32 + hl];
                    float gg = Gs[b * 132 + 64 + hl] + Gs[(64 + b) * 132 + 64 + hl]
                             + bias[64 + hl];
                    float go = Gs[b * 132 + 96 + hl] + Gs[(64 + b) * 132 + 96 + hl]
                             + bias[96 + hl];
                    float ig = sigf(gi), fg = sigf(gf), og = sigf(go);
                    float gt = tanhfast(gg);
                    float* cp_ = csm + b * 32 + hl;
                    float cn = fg * (*cp_) + ig * gt;
                    *cp_ = cn;
                    float hn = og * tanhfast(cn);
                    int H = n0 + hl;                 // 0..1023
                    size_t off = afrag_off(H >> 7, (H >> 4) & 7,
                                           b >> 4, b & 15, H & 15);
                    dstA[off] = __float2half(hn);
                    if (t == Tlen - 1 && L == Lnum - 1)
                        g_hfin[(size_t)b * Hdim + H] = hn;
                }
            }
        }
        grid_sync();   // orders h writes; IVALL kills stale L1 A lines
    }
    #undef BOFF
}

__global__ void fc_kernel(const float* __restrict__ Wfc,
                          const float* __restrict__ bfc,
                          float* __restrict__ out)
{
    const float* h = g_hfin;
    int warp = (blockIdx.x * blockDim.x + threadIdx.x) >> 5;
    int lane = threadIdx.x & 31;
    int b = warp >> 9;
    int o = warp & (Odim - 1);
    const float4* hv = (const float4*)(h   + (size_t)b * Hdim);
    const float4* wv = (const float4*)(Wfc + (size_t)o * Hdim);
    float s = 0.f;
    #pragma unroll
    for (int it = 0; it < 8; ++it) {
        float4 a = hv[it * 32 + lane];
        float4 w = wv[it * 32 + lane];
        s += a.x * w.x + a.y * w.y + a.z * w.z + a.w * w.w;
    }
    #pragma unroll
    for (int off = 16; off; off >>= 1)
        s += __shfl_xor_sync(0xffffffffu, s, off);
    if (lane == 0)
        out[(size_t)b * Odim + o] = s + bfc[o];
}

extern "C" void kernel_launch(void* const* d_in, const int* in_sizes, int n_in,
                              void* d_out, int out_size)
{
    const float* x   = (const float*)d_in[0];
    const float* Wih = (const float*)d_in[1];
    const float* Whh = (const float*)d_in[2];
    const float* bih = (const float*)d_in[3];
    const float* bhh = (const float*)d_in[4];
    const float* Wfc = (const float*)d_in[5];
    const float* bfc = (const float*)d_in[6];
    float* out = (float*)d_out;

    cudaFuncSetAttribute(lstm_persistent,
                         cudaFuncAttributeMaxDynamicSharedMemorySize, SMEM_DYN);

    zero_ha<<<512, 1024>>>();
    prep_x<<<16384, 1024>>>(x);
    prep_weights<<<16384, 1024>>>(Wih, Whh);
    lstm_persistent<<<NBLK, NTHR, SMEM_DYN>>>(bih, bhh);
    fc_kernel<<<(Bsz * Odim) / 8, 256>>>(Wfc, bfc, out);
}